// round 15
// baseline (speedup 1.0000x reference)
#include <cuda_runtime.h>
#include <cuda_fp16.h>
#include <math.h>
#include <stdint.h>

#define N_NODES   50000
#define IN_FEAT   128
#define HIDDEN    256
#define N_CLASSES 40
#define NC_PAD    64
#define MAX_E     320000
#define BN_EPS    1e-5f

// ---------------- scratch (device globals; zero-initialized at load) ----------------
__device__ __align__(16) __half g_xh [N_NODES * IN_FEAT];
__device__ __align__(16) __half g_h1 [N_NODES * IN_FEAT];
__device__ __align__(16) __half g_xw1[N_NODES * HIDDEN];
__device__ __align__(16) __half g_xw2[N_NODES * HIDDEN];
__device__ __align__(16) __half g_h2 [N_NODES * HIDDEN];
__device__ __align__(16) __half g_xw3[N_NODES * N_CLASSES];
// pre-split weights (hi/lo fp16); W3 padded to 64 cols
__device__ __align__(16) __half g_w1h[IN_FEAT * HIDDEN];
__device__ __align__(16) __half g_w1l[IN_FEAT * HIDDEN];
__device__ __align__(16) __half g_w2h[HIDDEN * HIDDEN];
__device__ __align__(16) __half g_w2l[HIDDEN * HIDDEN];
__device__ __align__(16) __half g_w3h[HIDDEN * NC_PAD];
__device__ __align__(16) __half g_w3l[HIDDEN * NC_PAD];
__device__ float g_dinv[N_NODES];
__device__ int   g_cnt[N_NODES];
__device__ int   g_rowstart[N_NODES];
__device__ int   g_cursor[N_NODES];
__device__ int   g_total;
__device__ int2  g_edge[MAX_E];
__device__ float g_sum1[HIDDEN];
__device__ float g_sumsq1[HIDDEN];
__device__ float g_sum2[HIDDEN];
__device__ float g_sumsq2[HIDDEN];

// ---------------- per-block edge dtype probe ----------------
__device__ __forceinline__ int probe_is64(const int* ei32) {
    int probe = ei32[2 * (threadIdx.x & 127) + 1];
    return (__syncthreads_or(probe) == 0) ? 1 : 0;
}
__device__ __forceinline__ int eget(const void* ei, long pos, int is64) {
    if (is64) return (int)__ldg(((const long long*)ei) + pos);
    return __ldg(((const int*)ei) + pos);
}

// ---------------- fp16 pack/unpack ----------------
__device__ __forceinline__ void unpack4(uint2 v, float* f) {
    float2 t = __half22float2(*(__half2*)&v.x); f[0] = t.x; f[1] = t.y;
    t = __half22float2(*(__half2*)&v.y);        f[2] = t.x; f[3] = t.y;
}
__device__ __forceinline__ void unpack8(uint4 v, float* f) {
    float2 t;
    t = __half22float2(*(__half2*)&v.x); f[0] = t.x; f[1] = t.y;
    t = __half22float2(*(__half2*)&v.y); f[2] = t.x; f[3] = t.y;
    t = __half22float2(*(__half2*)&v.z); f[4] = t.x; f[5] = t.y;
    t = __half22float2(*(__half2*)&v.w); f[6] = t.x; f[7] = t.y;
}
__device__ __forceinline__ uint2 pack4(float f0, float f1, float f2, float f3) {
    __half2 h0 = __floats2half2_rn(f0, f1), h1 = __floats2half2_rn(f2, f3);
    uint2 r;
    r.x = *(uint32_t*)&h0; r.y = *(uint32_t*)&h1;
    return r;
}
__device__ __forceinline__ uint4 pack8(const float* f) {
    uint2 a = pack4(f[0], f[1], f[2], f[3]);
    uint2 b = pack4(f[4], f[5], f[6], f[7]);
    return make_uint4(a.x, a.y, b.x, b.y);
}
__device__ __forceinline__ void wsplit(float v, __half& h, __half& l) {
    h = __float2half_rn(v);
    l = __float2half_rn(v - __half2float(h));
}

// ---------------- preamble: histogram + x->fp16 + weight pre-split ----------------
#define W1_N (IN_FEAT * HIDDEN)
#define W2_N (HIDDEN * HIDDEN)
#define W3_N (HIDDEN * NC_PAD)
__global__ void k_pre(const void* __restrict__ ei, int E,
                      const float* __restrict__ x, __half* __restrict__ xh, long nfeat,
                      const float* __restrict__ W1, const float* __restrict__ W2,
                      const float* __restrict__ W3) {
    int is64 = probe_is64((const int*)ei);
    int t = blockIdx.x * blockDim.x + threadIdx.x;
    if (t < E) atomicAdd(&g_cnt[eget(ei, (long)E + t, is64)], 1);
    long i8 = (long)t * 8;
    if (i8 < nfeat) {
        float4 v0 = *(const float4*)&x[i8];
        float4 v1 = *(const float4*)&x[i8 + 4];
        float f[8] = {v0.x, v0.y, v0.z, v0.w, v1.x, v1.y, v1.z, v1.w};
        *(uint4*)&xh[i8] = pack8(f);
    }
    if (t < W1_N) wsplit(W1[t], g_w1h[t], g_w1l[t]);
    else if (t < W1_N + W2_N) {
        int i = t - W1_N;
        wsplit(W2[i], g_w2h[i], g_w2l[i]);
    } else if (t < W1_N + W2_N + W3_N) {
        int i = t - W1_N - W2_N;
        int col = i & (NC_PAD - 1);
        float v = (col < N_CLASSES) ? W3[(i >> 6) * N_CLASSES + col] : 0.0f;
        wsplit(v, g_w3h[i], g_w3l[i]);
    }
}
__global__ void k_reserve(int n) {
    int i = blockIdx.x * blockDim.x + threadIdx.x;
    if (i >= n) return;
    int c = g_cnt[i];
    g_dinv[i] = rsqrtf(1.0f + (float)c);
    int pos = atomicAdd(&g_total, c);
    g_rowstart[i] = pos;
    g_cursor[i] = pos;
}
__global__ void k_fill(const void* __restrict__ ei, int E) {
    int is64 = probe_is64((const int*)ei);
    int e = blockIdx.x * blockDim.x + threadIdx.x;
    if (e >= E) return;
    int s = eget(ei, e, is64);
    int d = eget(ei, (long)E + e, is64);
    int pos = atomicAdd(&g_cursor[d], 1);
    g_edge[pos] = make_int2(s, __float_as_int(g_dinv[s] * g_dinv[d]));
}

// ---------------- HMMA / cp.async helpers ----------------
__device__ __forceinline__ void ldm_x4(uint32_t* r, const void* p) {
    uint32_t a = (uint32_t)__cvta_generic_to_shared(p);
    asm volatile("ldmatrix.sync.aligned.m8n8.x4.shared.b16 {%0,%1,%2,%3}, [%4];"
                 : "=r"(r[0]), "=r"(r[1]), "=r"(r[2]), "=r"(r[3]) : "r"(a));
}
__device__ __forceinline__ void ldm_x4_t(uint32_t* r, const void* p) {
    uint32_t a = (uint32_t)__cvta_generic_to_shared(p);
    asm volatile("ldmatrix.sync.aligned.m8n8.x4.trans.shared.b16 {%0,%1,%2,%3}, [%4];"
                 : "=r"(r[0]), "=r"(r[1]), "=r"(r[2]), "=r"(r[3]) : "r"(a));
}
__device__ __forceinline__ void mma_f16(float* c, const uint32_t* a, const uint32_t* b) {
    asm volatile(
        "mma.sync.aligned.m16n8k16.row.col.f32.f16.f16.f32 "
        "{%0,%1,%2,%3}, {%4,%5,%6,%7}, {%8,%9}, {%0,%1,%2,%3};"
        : "+f"(c[0]), "+f"(c[1]), "+f"(c[2]), "+f"(c[3])
        : "r"(a[0]), "r"(a[1]), "r"(a[2]), "r"(a[3]), "r"(b[0]), "r"(b[1]));
}
#define CP16(dst, src) \
    asm volatile("cp.async.cg.shared.global [%0], [%1], 16;" :: "r"(dst), "l"(src))
#define CP_COMMIT() asm volatile("cp.async.commit_group;" ::: "memory")
#define CP_WAIT0()  asm volatile("cp.async.wait_group 0;" ::: "memory")

// ---------------- f16 HMMA GEMM: BM=128, BN_T=64, 3 CTAs/SM, cp.async B ----------
// xw = f16( act(A) @ [Wh+Wl] (+ bias) ); A fp16 exact; Wh/Wl pre-split fp16.
template <bool DO_STATS>
__global__ void __launch_bounds__(256, 3) gemm_h(
    const __half* __restrict__ A,
    const __half* __restrict__ Wh, const __half* __restrict__ Wl,
    const float* __restrict__ bnsum, const float* __restrict__ bnsumsq,
    const float* __restrict__ gamma, const float* __restrict__ beta,
    const float* __restrict__ bias,
    float* __restrict__ osum, float* __restrict__ osumsq,
    __half* __restrict__ xw,
    int M, int K, int Nr, int Npad)
{
    constexpr int BM = 128, BK = 32, BN_T = 64;
    constexpr int ASTR = BK + 8;            // 40 halves
    constexpr int BSTR = BN_T + 8;          // 72 halves
    constexpr int BN_W = BN_T / 2;          // 32 (warps 4x2)
    constexpr int NT = BN_W / 8;            // 4
    constexpr int NG = BN_W / 16;           // 2
    constexpr int CPR = BN_T / 8;           // 8 x 16B chunks per row
    constexpr int ABYTES = BM * ASTR * 2;   // 10240
    constexpr int BBYTES = BK * BSTR * 2;   // 4608
    constexpr int STAGE  = ABYTES + 2 * BBYTES;  // 19456

    extern __shared__ char dsm[];
    __shared__ float sSc[HIDDEN], sSh[HIDDEN];
    const uint32_t sb = (uint32_t)__cvta_generic_to_shared(dsm);

    const int tid = threadIdx.x;
    const int wid = tid >> 5, lane = tid & 31;
    const int warp_m = wid >> 1, warp_n = wid & 1;
    const int blockRow = blockIdx.x * BM;
    const int colBase = blockIdx.y * BN_T;
    const bool useScale = (gamma != nullptr);

    auto AHp = [&](int s) { return (__half*)(dsm + s * STAGE); };
    auto BHp = [&](int s) { return (__half*)(dsm + s * STAGE + ABYTES); };
    auto BLp = [&](int s) { return (__half*)(dsm + s * STAGE + ABYTES + BBYTES); };

    const int a_row = tid >> 1;
    const int a_h   = (tid & 1) * 16;
    uint4 pa[2];

    auto ldgA = [&](int k0) {
        long gr = blockRow + a_row;
        if (gr < M) {
            pa[0] = *(const uint4*)&A[gr * K + k0 + a_h];
            pa[1] = *(const uint4*)&A[gr * K + k0 + a_h + 8];
        } else {
            pa[0] = make_uint4(0, 0, 0, 0);
            pa[1] = make_uint4(0, 0, 0, 0);
        }
    };
    auto cvtA = [&](int s, int k0) {
        __half* AH = AHp(s);
        if (!useScale) {
            *(uint4*)&AH[a_row * ASTR + a_h]     = pa[0];
            *(uint4*)&AH[a_row * ASTR + a_h + 8] = pa[1];
        } else {
            float f[16];
            unpack8(pa[0], f);
            unpack8(pa[1], f + 8);
#pragma unroll
            for (int j = 0; j < 16; j++) {
                int k = k0 + a_h + j;
                f[j] = fmaxf(0.0f, fmaf(f[j], sSc[k], sSh[k]));
            }
            *(uint4*)&AH[a_row * ASTR + a_h]     = pack8(f);
            *(uint4*)&AH[a_row * ASTR + a_h + 8] = pack8(f + 8);
        }
    };
    // cp.async both B arrays (BK*CPR = 256 chunks exactly -> one per thread)
    auto issueB = [&](int s, int k0) {
        uint32_t base = sb + s * STAGE + ABYTES;
        int row = tid / CPR;
        int c8  = tid - row * CPR;
        long so = (long)(k0 + row) * Npad + colBase + c8 * 8;
        uint32_t d = base + (uint32_t)(row * BSTR + c8 * 8) * 2;
        CP16(d, Wh + so);
        CP16(d + BBYTES, Wl + so);
        CP_COMMIT();
    };

    float acc[2][NT][4];
#pragma unroll
    for (int m = 0; m < 2; m++)
#pragma unroll
        for (int n = 0; n < NT; n++)
#pragma unroll
            for (int j = 0; j < 4; j++) acc[m][n][j] = 0.0f;

    auto doMMA = [&](int s) {
        __half* AH = AHp(s);
        __half* BH = BHp(s);
        __half* BL = BLp(s);
#pragma unroll
        for (int ks = 0; ks < 2; ks++) {
            uint32_t av[2][4];
#pragma unroll
            for (int tm = 0; tm < 2; tm++) {
                int r = warp_m * 32 + tm * 16 + (lane & 15);
                int cc = ks * 16 + (lane >> 4) * 8;
                ldm_x4(av[tm], &AH[r * ASTR + cc]);
            }
            uint32_t bh[NG][4], bl[NG][4];
#pragma unroll
            for (int ng = 0; ng < NG; ng++) {
                int r = ks * 16 + (lane & 15);
                int cc = warp_n * BN_W + ng * 16 + (lane >> 4) * 8;
                ldm_x4_t(bh[ng], &BH[r * BSTR + cc]);
                ldm_x4_t(bl[ng], &BL[r * BSTR + cc]);
            }
#pragma unroll
            for (int tm = 0; tm < 2; tm++)
#pragma unroll
                for (int nn = 0; nn < NT; nn++) {
                    const uint32_t* bH = &bh[nn >> 1][(nn & 1) * 2];
                    const uint32_t* bL = &bl[nn >> 1][(nn & 1) * 2];
                    mma_f16(acc[tm][nn], av[tm], bH);
                    mma_f16(acc[tm][nn], av[tm], bL);
                }
        }
    };

    // ---- prologue ----
    ldgA(0);
    issueB(0, 0);
    if (useScale) {
        const float inv_n = 1.0f / (float)M;
        for (int i = tid; i < K; i += 256) {
            float mean = bnsum[i] * inv_n;
            float var  = bnsumsq[i] * inv_n - mean * mean;
            float sc = __ldg(&gamma[i]) * rsqrtf(var + BN_EPS);
            sSc[i] = sc;
            sSh[i] = __ldg(&beta[i]) - mean * sc;
        }
        __syncthreads();
    }
    cvtA(0, 0);

    const int nc = K / BK;
    for (int c = 0; c < nc; c++) {
        CP_WAIT0();
        __syncthreads();
        const bool more = (c + 1 < nc);
        if (more) {
            ldgA((c + 1) * BK);
            issueB((c + 1) & 1, (c + 1) * BK);
        }
        doMMA(c & 1);
        if (more) cvtA((c + 1) & 1, (c + 1) * BK);
    }

    // ---- epilogue ----
    const int warpCol = colBase + warp_n * BN_W;
    float ls[NT][2], lss[NT][2];
    if (DO_STATS) {
#pragma unroll
        for (int n = 0; n < NT; n++) {
            ls[n][0] = ls[n][1] = 0.0f;
            lss[n][0] = lss[n][1] = 0.0f;
        }
    }
#pragma unroll
    for (int tm = 0; tm < 2; tm++) {
        int r0 = blockRow + warp_m * 32 + tm * 16 + (lane >> 2);
#pragma unroll
        for (int h = 0; h < 2; h++) {
            long row = r0 + h * 8;
            if (row >= M) continue;
#pragma unroll
            for (int nn = 0; nn < NT; nn++) {
                int col = warpCol + nn * 8 + (lane & 3) * 2;
                if (col >= Nr) continue;
                float2 v = make_float2(acc[tm][nn][h * 2], acc[tm][nn][h * 2 + 1]);
                if (bias) {
                    v.x += __ldg(&bias[col]);
                    v.y += __ldg(&bias[col + 1]);
                }
                *(__half2*)&xw[row * Nr + col] = __floats2half2_rn(v.x, v.y);
                if (DO_STATS) {
                    ls[nn][0] += v.x;  lss[nn][0] += v.x * v.x;
                    ls[nn][1] += v.y;  lss[nn][1] += v.y * v.y;
                }
            }
        }
    }
    if (DO_STATS) {
#pragma unroll
        for (int nn = 0; nn < NT; nn++)
#pragma unroll
            for (int j = 0; j < 2; j++) {
#pragma unroll
                for (int mask = 4; mask < 32; mask <<= 1) {
                    ls[nn][j]  += __shfl_xor_sync(0xFFFFFFFFu, ls[nn][j], mask);
                    lss[nn][j] += __shfl_xor_sync(0xFFFFFFFFu, lss[nn][j], mask);
                }
            }
        if (lane < 4) {
#pragma unroll
            for (int nn = 0; nn < NT; nn++) {
                int col = warpCol + nn * 8 + lane * 2;
                atomicAdd(&osum[col],       ls[nn][0]);
                atomicAdd(&osum[col + 1],   ls[nn][1]);
                atomicAdd(&osumsq[col],     lss[nn][0]);
                atomicAdd(&osumsq[col + 1], lss[nn][1]);
            }
        }
    }
}

// ---------------- gathers (R11 proven) ----------------
__global__ void k_gather128h(__half* __restrict__ out, const __half* __restrict__ xh, int n) {
    int node = (blockIdx.x * blockDim.x + threadIdx.x) >> 5;
    int lane = threadIdx.x & 31;
    if (node >= n) return;
    float dv = g_dinv[node];
    float dv2 = dv * dv;
    const uint2* rows = (const uint2*)xh;
    float a[4], f[4];
    unpack4(__ldg(&rows[(long)node * 32 + lane]), a);
#pragma unroll
    for (int j = 0; j < 4; j++) a[j] *= dv2;
    int b = g_rowstart[node], e = b + g_cnt[node];
    int p = b;
    for (; p + 3 < e; p += 4) {
        int2 e0 = __ldg(&g_edge[p]),     e1 = __ldg(&g_edge[p + 1]);
        int2 e2 = __ldg(&g_edge[p + 2]), e3 = __ldg(&g_edge[p + 3]);
        uint2 v0 = __ldg(&rows[(long)e0.x * 32 + lane]);
        uint2 v1 = __ldg(&rows[(long)e1.x * 32 + lane]);
        uint2 v2 = __ldg(&rows[(long)e2.x * 32 + lane]);
        uint2 v3 = __ldg(&rows[(long)e3.x * 32 + lane]);
        unpack4(v0, f);
#pragma unroll
        for (int j = 0; j < 4; j++) a[j] = fmaf(__int_as_float(e0.y), f[j], a[j]);
        unpack4(v1, f);
#pragma unroll
        for (int j = 0; j < 4; j++) a[j] = fmaf(__int_as_float(e1.y), f[j], a[j]);
        unpack4(v2, f);
#pragma unroll
        for (int j = 0; j < 4; j++) a[j] = fmaf(__int_as_float(e2.y), f[j], a[j]);
        unpack4(v3, f);
#pragma unroll
        for (int j = 0; j < 4; j++) a[j] = fmaf(__int_as_float(e3.y), f[j], a[j]);
    }
    for (; p < e; p++) {
        int2 ee = __ldg(&g_edge[p]);
        unpack4(__ldg(&rows[(long)ee.x * 32 + lane]), f);
#pragma unroll
        for (int j = 0; j < 4; j++) a[j] = fmaf(__int_as_float(ee.y), f[j], a[j]);
    }
    ((uint2*)out)[(long)node * 32 + lane] = pack4(a[0], a[1], a[2], a[3]);
}

__global__ void k_gather256h(__half* __restrict__ out, const __half* __restrict__ xw,
                             const float* __restrict__ bias, int n) {
    int node = (blockIdx.x * blockDim.x + threadIdx.x) >> 5;
    int lane = threadIdx.x & 31;
    if (node >= n) return;
    float dv = g_dinv[node];
    float dv2 = dv * dv;
    const uint4* rows = (const uint4*)xw;
    float a[8], f[8];
    unpack8(__ldg(&rows[(long)node * 32 + lane]), a);
#pragma unroll
    for (int j = 0; j < 8; j++) a[j] *= dv2;
    int b = g_rowstart[node], e = b + g_cnt[node];
    int p = b;
    for (; p + 1 < e; p += 2) {
        int2 eA = __ldg(&g_edge[p]), eB = __ldg(&g_edge[p + 1]);
        uint4 vA = __ldg(&rows[(long)eA.x * 32 + lane]);
        uint4 vB = __ldg(&rows[(long)eB.x * 32 + lane]);
        unpack8(vA, f);
#pragma unroll
        for (int j = 0; j < 8; j++) a[j] = fmaf(__int_as_float(eA.y), f[j], a[j]);
        unpack8(vB, f);
#pragma unroll
        for (int j = 0; j < 8; j++) a[j] = fmaf(__int_as_float(eB.y), f[j], a[j]);
    }
    if (p < e) {
        int2 ee = __ldg(&g_edge[p]);
        unpack8(__ldg(&rows[(long)ee.x * 32 + lane]), f);
#pragma unroll
        for (int j = 0; j < 8; j++) a[j] = fmaf(__int_as_float(ee.y), f[j], a[j]);
    }
    const float4* b4 = (const float4*)bias;
    float4 bb0 = __ldg(&b4[2 * lane]);
    float4 bb1 = __ldg(&b4[2 * lane + 1]);
    a[0] += bb0.x; a[1] += bb0.y; a[2] += bb0.z; a[3] += bb0.w;
    a[4] += bb1.x; a[5] += bb1.y; a[6] += bb1.z; a[7] += bb1.w;
    ((uint4*)out)[(long)node * 32 + lane] = pack8(a);
}

// ---------------- BN2 stats ----------------
__global__ void k_bn_stats_h(const __half* __restrict__ h, int n) {
    int c = threadIdx.x;
    int chunk = (n + gridDim.x - 1) / gridDim.x;
    int r0 = blockIdx.x * chunk;
    int r1 = min(n, r0 + chunk);
    float s = 0.0f, ss = 0.0f;
    for (int r = r0; r < r1; r++) {
        float v = __half2float(h[(long)r * HIDDEN + c]);
        s += v;
        ss += v * v;
    }
    atomicAdd(&g_sum2[c], s);
    atomicAdd(&g_sumsq2[c], ss);
}

// ---------------- width-40 gather + bias + log_softmax; self-cleans scratch ----------
__global__ void k_gather40_lsm(float* __restrict__ out, const __half* __restrict__ xw,
                               const float* __restrict__ bias, int n) {
    int gtid = blockIdx.x * blockDim.x + threadIdx.x;
    if (gtid < HIDDEN) {
        g_sum1[gtid] = 0.0f; g_sumsq1[gtid] = 0.0f;
        g_sum2[gtid] = 0.0f; g_sumsq2[gtid] = 0.0f;
    }
    int node = gtid >> 5;
    int lane = threadIdx.x & 31;
    if (node >= n) return;
    bool act = (lane < N_CLASSES / 2);
    float dv = g_dinv[node];
    float dv2 = dv * dv;
    float a0 = 0.0f, a1 = 0.0f;
    if (act) {
        float2 sv = __half22float2(__ldg((const __half2*)(xw + (long)node * N_CLASSES) + lane));
        a0 = dv2 * sv.x; a1 = dv2 * sv.y;
    }
    int b = g_rowstart[node], e = b + g_cnt[node];
    int p = b;
    for (; p + 1 < e; p += 2) {
        int2 eA = __ldg(&g_edge[p]), eB = __ldg(&g_edge[p + 1]);
        if (act) {
            float2 va = __half22float2(__ldg((const __half2*)(xw + (long)eA.x * N_CLASSES) + lane));
            float2 vb = __half22float2(__ldg((const __half2*)(xw + (long)eB.x * N_CLASSES) + lane));
            float nA = __int_as_float(eA.y), nB = __int_as_float(eB.y);
            a0 = fmaf(nA, va.x, fmaf(nB, vb.x, a0));
            a1 = fmaf(nA, va.y, fmaf(nB, vb.y, a1));
        }
    }
    if (p < e) {
        int2 ee = __ldg(&g_edge[p]);
        if (act) {
            float2 va = __half22float2(__ldg((const __half2*)(xw + (long)ee.x * N_CLASSES) + lane));
            float nA = __int_as_float(ee.y);
            a0 = fmaf(nA, va.x, a0);
            a1 = fmaf(nA, va.y, a1);
        }
    }
    if (act) {
        a0 += __ldg(&bias[2 * lane]);
        a1 += __ldg(&bias[2 * lane + 1]);
    }
    float m = act ? fmaxf(a0, a1) : -1e30f;
#pragma unroll
    for (int o = 16; o > 0; o >>= 1)
        m = fmaxf(m, __shfl_xor_sync(0xFFFFFFFFu, m, o));
    float s = act ? (expf(a0 - m) + expf(a1 - m)) : 0.0f;
#pragma unroll
    for (int o = 16; o > 0; o >>= 1)
        s += __shfl_xor_sync(0xFFFFFFFFu, s, o);
    float lse = m + logf(s);
    if (act) {
        float* orow = out + (long)node * N_CLASSES;
        orow[2 * lane]     = a0 - lse;
        orow[2 * lane + 1] = a1 - lse;
    }
    if (lane == 0) g_cnt[node] = 0;
    if (node == 0 && lane == 0) g_total = 0;
}

// ---------------- launch ----------------
#define SMEM_GEMM  (2 * (128 * 40 * 2 + 2 * 32 * 72 * 2))   // 38912

extern "C" void kernel_launch(void* const* d_in, const int* in_sizes, int n_in,
                              void* d_out, int out_size) {
    const float* x   = (const float*)d_in[0];
    const void*  ei  = d_in[1];
    const float* W1  = (const float*)d_in[2];
    const float* b1  = (const float*)d_in[3];
    const float* g1  = (const float*)d_in[4];
    const float* be1 = (const float*)d_in[5];
    const float* W2  = (const float*)d_in[6];
    const float* b2  = (const float*)d_in[7];
    const float* g2  = (const float*)d_in[8];
    const float* be2 = (const float*)d_in[9];
    const float* W3  = (const float*)d_in[10];
    const float* b3  = (const float*)d_in[11];
    float* out = (float*)d_out;

    const int N = N_NODES;
    const int E = in_sizes[1] / 2;

    __half *pXh, *pH1, *pX1, *pX2, *pH2, *pX3;
    __half *pW1h, *pW1l, *pW2h, *pW2l, *pW3h, *pW3l;
    float *pS1, *pQ1, *pS2, *pQ2;
    cudaGetSymbolAddress((void**)&pXh, g_xh);
    cudaGetSymbolAddress((void**)&pH1, g_h1);
    cudaGetSymbolAddress((void**)&pX1, g_xw1);
    cudaGetSymbolAddress((void**)&pX2, g_xw2);
    cudaGetSymbolAddress((void**)&pH2, g_h2);
    cudaGetSymbolAddress((void**)&pX3, g_xw3);
    cudaGetSymbolAddress((void**)&pW1h, g_w1h);
    cudaGetSymbolAddress((void**)&pW1l, g_w1l);
    cudaGetSymbolAddress((void**)&pW2h, g_w2h);
    cudaGetSymbolAddress((void**)&pW2l, g_w2l);
    cudaGetSymbolAddress((void**)&pW3h, g_w3h);
    cudaGetSymbolAddress((void**)&pW3l, g_w3l);
    cudaGetSymbolAddress((void**)&pS1, g_sum1);
    cudaGetSymbolAddress((void**)&pQ1, g_sumsq1);
    cudaGetSymbolAddress((void**)&pS2, g_sum2);
    cudaGetSymbolAddress((void**)&pQ2, g_sumsq2);

    cudaFuncSetAttribute(gemm_h<true>,
                         cudaFuncAttributeMaxDynamicSharedMemorySize, SMEM_GEMM);
    cudaFuncSetAttribute(gemm_h<false>,
                         cudaFuncAttributeMaxDynamicSharedMemorySize, SMEM_GEMM);

    // ---- preamble (3 launches) ----
    long nfeat = (long)N * IN_FEAT;
    int cvtBlocks = (int)((nfeat / 8 + 255) / 256);
    int wBlocks = (W1_N + W2_N + W3_N + 255) / 256;
    int preBlocks = max(max(cvtBlocks, (E + 255) / 256), wBlocks);
    k_pre<<<preBlocks, 256>>>(ei, E, x, pXh, nfeat, W1, W2, W3);
    k_reserve<<<(N + 255) / 256, 256>>>(N);
    k_fill<<<(E + 255) / 256, 256>>>(ei, E);

    const int mTiles = (N + 127) / 128;
    dim3 gHid(mTiles, HIDDEN / 64);   // 391 x 4
    dim3 gCls(mTiles, 1);
    int gatherBlocks = (N * 32 + 255) / 256;

    // ---- layer 1: h1 = (AX)W1 + b1 ; BN1 stats in epilogue ----
    k_gather128h<<<gatherBlocks, 256>>>(pH1, pXh, N);
    gemm_h<true><<<gHid, 256, SMEM_GEMM>>>(
        pH1, pW1h, pW1l, nullptr, nullptr, nullptr, nullptr, b1, pS1, pQ1, pX1,
        N, IN_FEAT, HIDDEN, HIDDEN);

    // ---- layer 2: BN1 finalize in prologue; gather + bias; BN2 stats ----
    gemm_h<false><<<gHid, 256, SMEM_GEMM>>>(
        pX1, pW2h, pW2l, pS1, pQ1, g1, be1, nullptr, nullptr, nullptr, pX2,
        N, HIDDEN, HIDDEN, HIDDEN);
    k_gather256h<<<gatherBlocks, 256>>>(pH2, pX2, b2, N);
    k_bn_stats_h<<<512, HIDDEN>>>(pH2, N);

    // ---- layer 3: BN2 finalize in prologue; gather + lsm fused ----
    gemm_h<false><<<gCls, 256, SMEM_GEMM>>>(
        pH2, pW3h, pW3l, pS2, pQ2, g2, be2, nullptr, nullptr, nullptr, pX3,
        N, HIDDEN, N_CLASSES, NC_PAD);
    k_gather40_lsm<<<gatherBlocks, 256>>>(out, pX3, b3, N);
}

// round 16
// speedup vs baseline: 1.1826x; 1.1826x over previous
#include <cuda_runtime.h>
#include <cuda_fp16.h>
#include <math.h>
#include <stdint.h>

#define N_NODES   50000
#define IN_FEAT   128
#define HIDDEN    256
#define N_CLASSES 40
#define NC_PAD    64
#define MAX_E     320000
#define BN_EPS    1e-5f

// ---------------- scratch (device globals; zero-initialized at load) ----------------
__device__ __align__(16) __half g_xh [N_NODES * IN_FEAT];
__device__ __align__(16) __half g_h1 [N_NODES * IN_FEAT];
__device__ __align__(16) __half g_xw1[N_NODES * HIDDEN];
__device__ __align__(16) __half g_xw2[N_NODES * HIDDEN];
__device__ __align__(16) __half g_h2 [N_NODES * HIDDEN];
__device__ __align__(16) __half g_xw3[N_NODES * N_CLASSES];
// pre-converted fp16 weights; W3 padded to 64 cols
__device__ __align__(16) __half g_w1h[IN_FEAT * HIDDEN];
__device__ __align__(16) __half g_w2h[HIDDEN * HIDDEN];
__device__ __align__(16) __half g_w3h[HIDDEN * NC_PAD];
__device__ float g_dinv[N_NODES];
__device__ int   g_cnt[N_NODES];
__device__ int   g_rowstart[N_NODES];
__device__ int   g_cursor[N_NODES];
__device__ int   g_total;
__device__ int2  g_edge[MAX_E];
__device__ float g_sum1[HIDDEN];
__device__ float g_sumsq1[HIDDEN];
__device__ float g_sum2[HIDDEN];
__device__ float g_sumsq2[HIDDEN];

// ---------------- per-block edge dtype probe ----------------
__device__ __forceinline__ int probe_is64(const int* ei32) {
    int probe = ei32[2 * (threadIdx.x & 127) + 1];
    return (__syncthreads_or(probe) == 0) ? 1 : 0;
}
__device__ __forceinline__ int eget(const void* ei, long pos, int is64) {
    if (is64) return (int)__ldg(((const long long*)ei) + pos);
    return __ldg(((const int*)ei) + pos);
}

// ---------------- fp16 pack/unpack ----------------
__device__ __forceinline__ void unpack4(uint2 v, float* f) {
    float2 t = __half22float2(*(__half2*)&v.x); f[0] = t.x; f[1] = t.y;
    t = __half22float2(*(__half2*)&v.y);        f[2] = t.x; f[3] = t.y;
}
__device__ __forceinline__ void unpack8(uint4 v, float* f) {
    float2 t;
    t = __half22float2(*(__half2*)&v.x); f[0] = t.x; f[1] = t.y;
    t = __half22float2(*(__half2*)&v.y); f[2] = t.x; f[3] = t.y;
    t = __half22float2(*(__half2*)&v.z); f[4] = t.x; f[5] = t.y;
    t = __half22float2(*(__half2*)&v.w); f[6] = t.x; f[7] = t.y;
}
__device__ __forceinline__ uint2 pack4(float f0, float f1, float f2, float f3) {
    __half2 h0 = __floats2half2_rn(f0, f1), h1 = __floats2half2_rn(f2, f3);
    uint2 r;
    r.x = *(uint32_t*)&h0; r.y = *(uint32_t*)&h1;
    return r;
}
__device__ __forceinline__ uint4 pack8(const float* f) {
    uint2 a = pack4(f[0], f[1], f[2], f[3]);
    uint2 b = pack4(f[4], f[5], f[6], f[7]);
    return make_uint4(a.x, a.y, b.x, b.y);
}

// ---------------- preamble: histogram + x->fp16 + weight convert ----------------
#define W1_N (IN_FEAT * HIDDEN)
#define W2_N (HIDDEN * HIDDEN)
#define W3_N (HIDDEN * NC_PAD)
__global__ void k_pre(const void* __restrict__ ei, int E,
                      const float* __restrict__ x, __half* __restrict__ xh, long nfeat,
                      const float* __restrict__ W1, const float* __restrict__ W2,
                      const float* __restrict__ W3) {
    int is64 = probe_is64((const int*)ei);
    int t = blockIdx.x * blockDim.x + threadIdx.x;
    if (t < E) atomicAdd(&g_cnt[eget(ei, (long)E + t, is64)], 1);
    long i8 = (long)t * 8;
    if (i8 < nfeat) {
        float4 v0 = *(const float4*)&x[i8];
        float4 v1 = *(const float4*)&x[i8 + 4];
        float f[8] = {v0.x, v0.y, v0.z, v0.w, v1.x, v1.y, v1.z, v1.w};
        *(uint4*)&xh[i8] = pack8(f);
    }
    if (t < W1_N) g_w1h[t] = __float2half_rn(W1[t]);
    else if (t < W1_N + W2_N) {
        int i = t - W1_N;
        g_w2h[i] = __float2half_rn(W2[i]);
    } else if (t < W1_N + W2_N + W3_N) {
        int i = t - W1_N - W2_N;
        int col = i & (NC_PAD - 1);
        float v = (col < N_CLASSES) ? W3[(i >> 6) * N_CLASSES + col] : 0.0f;
        g_w3h[i] = __float2half_rn(v);
    }
}
__global__ void k_reserve(int n) {
    int i = blockIdx.x * blockDim.x + threadIdx.x;
    if (i >= n) return;
    int c = g_cnt[i];
    g_dinv[i] = rsqrtf(1.0f + (float)c);
    int pos = atomicAdd(&g_total, c);
    g_rowstart[i] = pos;
    g_cursor[i] = pos;
}
__global__ void k_fill(const void* __restrict__ ei, int E) {
    int is64 = probe_is64((const int*)ei);
    int e = blockIdx.x * blockDim.x + threadIdx.x;
    if (e >= E) return;
    int s = eget(ei, e, is64);
    int d = eget(ei, (long)E + e, is64);
    int pos = atomicAdd(&g_cursor[d], 1);
    g_edge[pos] = make_int2(s, __float_as_int(g_dinv[s] * g_dinv[d]));
}

// ---------------- HMMA / cp.async helpers ----------------
__device__ __forceinline__ void ldm_x4(uint32_t* r, const void* p) {
    uint32_t a = (uint32_t)__cvta_generic_to_shared(p);
    asm volatile("ldmatrix.sync.aligned.m8n8.x4.shared.b16 {%0,%1,%2,%3}, [%4];"
                 : "=r"(r[0]), "=r"(r[1]), "=r"(r[2]), "=r"(r[3]) : "r"(a));
}
__device__ __forceinline__ void ldm_x4_t(uint32_t* r, const void* p) {
    uint32_t a = (uint32_t)__cvta_generic_to_shared(p);
    asm volatile("ldmatrix.sync.aligned.m8n8.x4.trans.shared.b16 {%0,%1,%2,%3}, [%4];"
                 : "=r"(r[0]), "=r"(r[1]), "=r"(r[2]), "=r"(r[3]) : "r"(a));
}
__device__ __forceinline__ void mma_f16(float* c, const uint32_t* a, const uint32_t* b) {
    asm volatile(
        "mma.sync.aligned.m16n8k16.row.col.f32.f16.f16.f32 "
        "{%0,%1,%2,%3}, {%4,%5,%6,%7}, {%8,%9}, {%0,%1,%2,%3};"
        : "+f"(c[0]), "+f"(c[1]), "+f"(c[2]), "+f"(c[3])
        : "r"(a[0]), "r"(a[1]), "r"(a[2]), "r"(a[3]), "r"(b[0]), "r"(b[1]));
}
#define CP16(dst, src) \
    asm volatile("cp.async.cg.shared.global [%0], [%1], 16;" :: "r"(dst), "l"(src))
#define CP_COMMIT() asm volatile("cp.async.commit_group;" ::: "memory")
#define CP_WAIT0()  asm volatile("cp.async.wait_group 0;" ::: "memory")

// ---------------- f16 HMMA GEMM: BM=128, cp.async B (fp16 weights), 2-stage --------
// xw = f16( act(A) @ W (+ bias) ); A fp16 exact; W pre-converted fp16 (single MMA).
template <int BN_T, bool DO_STATS>
__global__ void __launch_bounds__(256) gemm_h(
    const __half* __restrict__ A, const __half* __restrict__ Wh,
    const float* __restrict__ bnsum, const float* __restrict__ bnsumsq,
    const float* __restrict__ gamma, const float* __restrict__ beta,
    const float* __restrict__ bias,
    float* __restrict__ osum, float* __restrict__ osumsq,
    __half* __restrict__ xw,
    int M, int K, int Nr, int Npad)
{
    constexpr int BM = 128, BK = 32;
    constexpr int ASTR = BK + 8;
    constexpr int BSTR = BN_T + 8;
    constexpr int BN_W = BN_T / 2;
    constexpr int NT = BN_W / 8;
    constexpr int NG = BN_W / 16;
    constexpr int CPR = BN_T / 8;
    constexpr int CH_IT = (BK * CPR + 255) / 256;
    constexpr int ABYTES = BM * ASTR * 2;   // 10240
    constexpr int BBYTES = BK * BSTR * 2;
    constexpr int STAGE  = ABYTES + BBYTES;

    extern __shared__ char dsm[];
    __shared__ float sSc[HIDDEN], sSh[HIDDEN];
    const uint32_t sb = (uint32_t)__cvta_generic_to_shared(dsm);

    const int tid = threadIdx.x;
    const int wid = tid >> 5, lane = tid & 31;
    const int warp_m = wid >> 1, warp_n = wid & 1;   // 4 x 2
    const int blockRow = blockIdx.x * BM;
    const int colBase = blockIdx.y * BN_T;
    const bool useScale = (gamma != nullptr);

    auto AHp = [&](int s) { return (__half*)(dsm + s * STAGE); };
    auto BHp = [&](int s) { return (__half*)(dsm + s * STAGE + ABYTES); };

    const int a_row = tid >> 1;
    const int a_h   = (tid & 1) * 16;
    uint4 pa[2];

    auto ldgA = [&](int k0) {
        long gr = blockRow + a_row;
        if (gr < M) {
            pa[0] = *(const uint4*)&A[gr * K + k0 + a_h];
            pa[1] = *(const uint4*)&A[gr * K + k0 + a_h + 8];
        } else {
            pa[0] = make_uint4(0, 0, 0, 0);
            pa[1] = make_uint4(0, 0, 0, 0);
        }
    };
    auto cvtA = [&](int s, int k0) {
        __half* AH = AHp(s);
        if (!useScale) {
            *(uint4*)&AH[a_row * ASTR + a_h]     = pa[0];
            *(uint4*)&AH[a_row * ASTR + a_h + 8] = pa[1];
        } else {
            float f[16];
            unpack8(pa[0], f);
            unpack8(pa[1], f + 8);
#pragma unroll
            for (int j = 0; j < 16; j++) {
                int k = k0 + a_h + j;
                f[j] = fmaxf(0.0f, fmaf(f[j], sSc[k], sSh[k]));
            }
            *(uint4*)&AH[a_row * ASTR + a_h]     = pack8(f);
            *(uint4*)&AH[a_row * ASTR + a_h + 8] = pack8(f + 8);
        }
    };
    auto issueB = [&](int s, int k0) {
        uint32_t base = sb + s * STAGE + ABYTES;
#pragma unroll
        for (int i = 0; i < CH_IT; i++) {
            int idx = tid + i * 256;
            int row = idx / CPR;
            int c8  = idx - row * CPR;
            long so = (long)(k0 + row) * Npad + colBase + c8 * 8;
            uint32_t d = base + (uint32_t)(row * BSTR + c8 * 8) * 2;
            CP16(d, Wh + so);
        }
        CP_COMMIT();
    };

    float acc[2][NT][4];
#pragma unroll
    for (int m = 0; m < 2; m++)
#pragma unroll
        for (int n = 0; n < NT; n++)
#pragma unroll
            for (int j = 0; j < 4; j++) acc[m][n][j] = 0.0f;

    auto doMMA = [&](int s) {
        __half* AH = AHp(s);
        __half* BH = BHp(s);
#pragma unroll
        for (int ks = 0; ks < 2; ks++) {
            uint32_t av[2][4];
#pragma unroll
            for (int tm = 0; tm < 2; tm++) {
                int r = warp_m * 32 + tm * 16 + (lane & 15);
                int cc = ks * 16 + (lane >> 4) * 8;
                ldm_x4(av[tm], &AH[r * ASTR + cc]);
            }
            uint32_t bh[NG][4];
#pragma unroll
            for (int ng = 0; ng < NG; ng++) {
                int r = ks * 16 + (lane & 15);
                int cc = warp_n * BN_W + ng * 16 + (lane >> 4) * 8;
                ldm_x4_t(bh[ng], &BH[r * BSTR + cc]);
            }
#pragma unroll
            for (int tm = 0; tm < 2; tm++)
#pragma unroll
                for (int nn = 0; nn < NT; nn++)
                    mma_f16(acc[tm][nn], av[tm], &bh[nn >> 1][(nn & 1) * 2]);
        }
    };

    // ---- prologue ----
    ldgA(0);
    issueB(0, 0);
    if (useScale) {
        const float inv_n = 1.0f / (float)M;
        for (int i = tid; i < K; i += 256) {
            float mean = bnsum[i] * inv_n;
            float var  = bnsumsq[i] * inv_n - mean * mean;
            float sc = __ldg(&gamma[i]) * rsqrtf(var + BN_EPS);
            sSc[i] = sc;
            sSh[i] = __ldg(&beta[i]) - mean * sc;
        }
        __syncthreads();
    }
    cvtA(0, 0);

    const int nc = K / BK;
    for (int c = 0; c < nc; c++) {
        CP_WAIT0();
        __syncthreads();
        const bool more = (c + 1 < nc);
        if (more) {
            ldgA((c + 1) * BK);
            issueB((c + 1) & 1, (c + 1) * BK);
        }
        doMMA(c & 1);
        if (more) cvtA((c + 1) & 1, (c + 1) * BK);
    }

    // ---- epilogue ----
    const int warpCol = colBase + warp_n * BN_W;
    float ls[NT][2], lss[NT][2];
    if (DO_STATS) {
#pragma unroll
        for (int n = 0; n < NT; n++) {
            ls[n][0] = ls[n][1] = 0.0f;
            lss[n][0] = lss[n][1] = 0.0f;
        }
    }
#pragma unroll
    for (int tm = 0; tm < 2; tm++) {
        int r0 = blockRow + warp_m * 32 + tm * 16 + (lane >> 2);
#pragma unroll
        for (int h = 0; h < 2; h++) {
            long row = r0 + h * 8;
            if (row >= M) continue;
#pragma unroll
            for (int nn = 0; nn < NT; nn++) {
                int col = warpCol + nn * 8 + (lane & 3) * 2;
                if (col >= Nr) continue;
                float2 v = make_float2(acc[tm][nn][h * 2], acc[tm][nn][h * 2 + 1]);
                if (bias) {
                    v.x += __ldg(&bias[col]);
                    v.y += __ldg(&bias[col + 1]);
                }
                *(__half2*)&xw[row * Nr + col] = __floats2half2_rn(v.x, v.y);
                if (DO_STATS) {
                    ls[nn][0] += v.x;  lss[nn][0] += v.x * v.x;
                    ls[nn][1] += v.y;  lss[nn][1] += v.y * v.y;
                }
            }
        }
    }
    if (DO_STATS) {
#pragma unroll
        for (int nn = 0; nn < NT; nn++)
#pragma unroll
            for (int j = 0; j < 2; j++) {
#pragma unroll
                for (int mask = 4; mask < 32; mask <<= 1) {
                    ls[nn][j]  += __shfl_xor_sync(0xFFFFFFFFu, ls[nn][j], mask);
                    lss[nn][j] += __shfl_xor_sync(0xFFFFFFFFu, lss[nn][j], mask);
                }
            }
        if (lane < 4) {
#pragma unroll
            for (int nn = 0; nn < NT; nn++) {
                int col = warpCol + nn * 8 + lane * 2;
                atomicAdd(&osum[col],       ls[nn][0]);
                atomicAdd(&osum[col + 1],   ls[nn][1]);
                atomicAdd(&osumsq[col],     lss[nn][0]);
                atomicAdd(&osumsq[col + 1], lss[nn][1]);
            }
        }
    }
}

// ---------------- gathers (R11 proven) ----------------
__global__ void k_gather128h(__half* __restrict__ out, const __half* __restrict__ xh, int n) {
    int node = (blockIdx.x * blockDim.x + threadIdx.x) >> 5;
    int lane = threadIdx.x & 31;
    if (node >= n) return;
    float dv = g_dinv[node];
    float dv2 = dv * dv;
    const uint2* rows = (const uint2*)xh;
    float a[4], f[4];
    unpack4(__ldg(&rows[(long)node * 32 + lane]), a);
#pragma unroll
    for (int j = 0; j < 4; j++) a[j] *= dv2;
    int b = g_rowstart[node], e = b + g_cnt[node];
    int p = b;
    for (; p + 3 < e; p += 4) {
        int2 e0 = __ldg(&g_edge[p]),     e1 = __ldg(&g_edge[p + 1]);
        int2 e2 = __ldg(&g_edge[p + 2]), e3 = __ldg(&g_edge[p + 3]);
        uint2 v0 = __ldg(&rows[(long)e0.x * 32 + lane]);
        uint2 v1 = __ldg(&rows[(long)e1.x * 32 + lane]);
        uint2 v2 = __ldg(&rows[(long)e2.x * 32 + lane]);
        uint2 v3 = __ldg(&rows[(long)e3.x * 32 + lane]);
        unpack4(v0, f);
#pragma unroll
        for (int j = 0; j < 4; j++) a[j] = fmaf(__int_as_float(e0.y), f[j], a[j]);
        unpack4(v1, f);
#pragma unroll
        for (int j = 0; j < 4; j++) a[j] = fmaf(__int_as_float(e1.y), f[j], a[j]);
        unpack4(v2, f);
#pragma unroll
        for (int j = 0; j < 4; j++) a[j] = fmaf(__int_as_float(e2.y), f[j], a[j]);
        unpack4(v3, f);
#pragma unroll
        for (int j = 0; j < 4; j++) a[j] = fmaf(__int_as_float(e3.y), f[j], a[j]);
    }
    for (; p < e; p++) {
        int2 ee = __ldg(&g_edge[p]);
        unpack4(__ldg(&rows[(long)ee.x * 32 + lane]), f);
#pragma unroll
        for (int j = 0; j < 4; j++) a[j] = fmaf(__int_as_float(ee.y), f[j], a[j]);
    }
    ((uint2*)out)[(long)node * 32 + lane] = pack4(a[0], a[1], a[2], a[3]);
}

__global__ void k_gather256h(__half* __restrict__ out, const __half* __restrict__ xw,
                             const float* __restrict__ bias, int n) {
    int node = (blockIdx.x * blockDim.x + threadIdx.x) >> 5;
    int lane = threadIdx.x & 31;
    if (node >= n) return;
    float dv = g_dinv[node];
    float dv2 = dv * dv;
    const uint4* rows = (const uint4*)xw;
    float a[8], f[8];
    unpack8(__ldg(&rows[(long)node * 32 + lane]), a);
#pragma unroll
    for (int j = 0; j < 8; j++) a[j] *= dv2;
    int b = g_rowstart[node], e = b + g_cnt[node];
    int p = b;
    for (; p + 1 < e; p += 2) {
        int2 eA = __ldg(&g_edge[p]), eB = __ldg(&g_edge[p + 1]);
        uint4 vA = __ldg(&rows[(long)eA.x * 32 + lane]);
        uint4 vB = __ldg(&rows[(long)eB.x * 32 + lane]);
        unpack8(vA, f);
#pragma unroll
        for (int j = 0; j < 8; j++) a[j] = fmaf(__int_as_float(eA.y), f[j], a[j]);
        unpack8(vB, f);
#pragma unroll
        for (int j = 0; j < 8; j++) a[j] = fmaf(__int_as_float(eB.y), f[j], a[j]);
    }
    if (p < e) {
        int2 ee = __ldg(&g_edge[p]);
        unpack8(__ldg(&rows[(long)ee.x * 32 + lane]), f);
#pragma unroll
        for (int j = 0; j < 8; j++) a[j] = fmaf(__int_as_float(ee.y), f[j], a[j]);
    }
    const float4* b4 = (const float4*)bias;
    float4 bb0 = __ldg(&b4[2 * lane]);
    float4 bb1 = __ldg(&b4[2 * lane + 1]);
    a[0] += bb0.x; a[1] += bb0.y; a[2] += bb0.z; a[3] += bb0.w;
    a[4] += bb1.x; a[5] += bb1.y; a[6] += bb1.z; a[7] += bb1.w;
    ((uint4*)out)[(long)node * 32 + lane] = pack8(a);
}

// ---------------- BN2 stats ----------------
__global__ void k_bn_stats_h(const __half* __restrict__ h, int n) {
    int c = threadIdx.x;
    int chunk = (n + gridDim.x - 1) / gridDim.x;
    int r0 = blockIdx.x * chunk;
    int r1 = min(n, r0 + chunk);
    float s = 0.0f, ss = 0.0f;
    for (int r = r0; r < r1; r++) {
        float v = __half2float(h[(long)r * HIDDEN + c]);
        s += v;
        ss += v * v;
    }
    atomicAdd(&g_sum2[c], s);
    atomicAdd(&g_sumsq2[c], ss);
}

// ---------------- width-40 gather + bias + log_softmax; self-cleans scratch ----------
__global__ void k_gather40_lsm(float* __restrict__ out, const __half* __restrict__ xw,
                               const float* __restrict__ bias, int n) {
    int gtid = blockIdx.x * blockDim.x + threadIdx.x;
    if (gtid < HIDDEN) {
        g_sum1[gtid] = 0.0f; g_sumsq1[gtid] = 0.0f;
        g_sum2[gtid] = 0.0f; g_sumsq2[gtid] = 0.0f;
    }
    int node = gtid >> 5;
    int lane = threadIdx.x & 31;
    if (node >= n) return;
    bool act = (lane < N_CLASSES / 2);
    float dv = g_dinv[node];
    float dv2 = dv * dv;
    float a0 = 0.0f, a1 = 0.0f;
    if (act) {
        float2 sv = __half22float2(__ldg((const __half2*)(xw + (long)node * N_CLASSES) + lane));
        a0 = dv2 * sv.x; a1 = dv2 * sv.y;
    }
    int b = g_rowstart[node], e = b + g_cnt[node];
    int p = b;
    for (; p + 1 < e; p += 2) {
        int2 eA = __ldg(&g_edge[p]), eB = __ldg(&g_edge[p + 1]);
        if (act) {
            float2 va = __half22float2(__ldg((const __half2*)(xw + (long)eA.x * N_CLASSES) + lane));
            float2 vb = __half22float2(__ldg((const __half2*)(xw + (long)eB.x * N_CLASSES) + lane));
            float nA = __int_as_float(eA.y), nB = __int_as_float(eB.y);
            a0 = fmaf(nA, va.x, fmaf(nB, vb.x, a0));
            a1 = fmaf(nA, va.y, fmaf(nB, vb.y, a1));
        }
    }
    if (p < e) {
        int2 ee = __ldg(&g_edge[p]);
        if (act) {
            float2 va = __half22float2(__ldg((const __half2*)(xw + (long)ee.x * N_CLASSES) + lane));
            float nA = __int_as_float(ee.y);
            a0 = fmaf(nA, va.x, a0);
            a1 = fmaf(nA, va.y, a1);
        }
    }
    if (act) {
        a0 += __ldg(&bias[2 * lane]);
        a1 += __ldg(&bias[2 * lane + 1]);
    }
    float m = act ? fmaxf(a0, a1) : -1e30f;
#pragma unroll
    for (int o = 16; o > 0; o >>= 1)
        m = fmaxf(m, __shfl_xor_sync(0xFFFFFFFFu, m, o));
    float s = act ? (expf(a0 - m) + expf(a1 - m)) : 0.0f;
#pragma unroll
    for (int o = 16; o > 0; o >>= 1)
        s += __shfl_xor_sync(0xFFFFFFFFu, s, o);
    float lse = m + logf(s);
    if (act) {
        float* orow = out + (long)node * N_CLASSES;
        orow[2 * lane]     = a0 - lse;
        orow[2 * lane + 1] = a1 - lse;
    }
    if (lane == 0) g_cnt[node] = 0;
    if (node == 0 && lane == 0) g_total = 0;
}

// ---------------- launch ----------------
#define SMEM_GEMM_128  (2 * (128 * 40 * 2 + 32 * 136 * 2))   // 37888
#define SMEM_GEMM_64   (2 * (128 * 40 * 2 + 32 * 72 * 2))    // 29696

extern "C" void kernel_launch(void* const* d_in, const int* in_sizes, int n_in,
                              void* d_out, int out_size) {
    const float* x   = (const float*)d_in[0];
    const void*  ei  = d_in[1];
    const float* W1  = (const float*)d_in[2];
    const float* b1  = (const float*)d_in[3];
    const float* g1  = (const float*)d_in[4];
    const float* be1 = (const float*)d_in[5];
    const float* W2  = (const float*)d_in[6];
    const float* b2  = (const float*)d_in[7];
    const float* g2  = (const float*)d_in[8];
    const float* be2 = (const float*)d_in[9];
    const float* W3  = (const float*)d_in[10];
    const float* b3  = (const float*)d_in[11];
    float* out = (float*)d_out;

    const int N = N_NODES;
    const int E = in_sizes[1] / 2;

    __half *pXh, *pH1, *pX1, *pX2, *pH2, *pX3;
    __half *pW1h, *pW2h, *pW3h;
    float *pS1, *pQ1, *pS2, *pQ2;
    cudaGetSymbolAddress((void**)&pXh, g_xh);
    cudaGetSymbolAddress((void**)&pH1, g_h1);
    cudaGetSymbolAddress((void**)&pX1, g_xw1);
    cudaGetSymbolAddress((void**)&pX2, g_xw2);
    cudaGetSymbolAddress((void**)&pH2, g_h2);
    cudaGetSymbolAddress((void**)&pX3, g_xw3);
    cudaGetSymbolAddress((void**)&pW1h, g_w1h);
    cudaGetSymbolAddress((void**)&pW2h, g_w2h);
    cudaGetSymbolAddress((void**)&pW3h, g_w3h);
    cudaGetSymbolAddress((void**)&pS1, g_sum1);
    cudaGetSymbolAddress((void**)&pQ1, g_sumsq1);
    cudaGetSymbolAddress((void**)&pS2, g_sum2);
    cudaGetSymbolAddress((void**)&pQ2, g_sumsq2);

    cudaFuncSetAttribute(gemm_h<128, true>,
                         cudaFuncAttributeMaxDynamicSharedMemorySize, SMEM_GEMM_128);
    cudaFuncSetAttribute(gemm_h<128, false>,
                         cudaFuncAttributeMaxDynamicSharedMemorySize, SMEM_GEMM_128);
    cudaFuncSetAttribute(gemm_h<64, false>,
                         cudaFuncAttributeMaxDynamicSharedMemorySize, SMEM_GEMM_64);

    // ---- preamble (3 launches) ----
    long nfeat = (long)N * IN_FEAT;
    int cvtBlocks = (int)((nfeat / 8 + 255) / 256);
    int wBlocks = (W1_N + W2_N + W3_N + 255) / 256;
    int preBlocks = max(max(cvtBlocks, (E + 255) / 256), wBlocks);
    k_pre<<<preBlocks, 256>>>(ei, E, x, pXh, nfeat, W1, W2, W3);
    k_reserve<<<(N + 255) / 256, 256>>>(N);
    k_fill<<<(E + 255) / 256, 256>>>(ei, E);

    const int mTiles = (N + 127) / 128;
    dim3 gHid(mTiles, 2);
    dim3 gCls(mTiles, 1);
    int gatherBlocks = (N * 32 + 255) / 256;

    // ---- layer 1: h1 = (AX)W1 + b1 ; BN1 stats in epilogue ----
    k_gather128h<<<gatherBlocks, 256>>>(pH1, pXh, N);
    gemm_h<128, true><<<gHid, 256, SMEM_GEMM_128>>>(
        pH1, pW1h, nullptr, nullptr, nullptr, nullptr, b1, pS1, pQ1, pX1,
        N, IN_FEAT, HIDDEN, HIDDEN);

    // ---- layer 2: BN1 finalize in prologue; gather + bias; BN2 stats ----
    gemm_h<128, false><<<gHid, 256, SMEM_GEMM_128>>>(
        pX1, pW2h, pS1, pQ1, g1, be1, nullptr, nullptr, nullptr, pX2,
        N, HIDDEN, HIDDEN, HIDDEN);
    k_gather256h<<<gatherBlocks, 256>>>(pH2, pX2, b2, N);
    k_bn_stats_h<<<512, HIDDEN>>>(pH2, N);

    // ---- layer 3: BN2 finalize in prologue; gather + lsm fused ----
    gemm_h<64, false><<<gCls, 256, SMEM_GEMM_64>>>(
        pH2, pW3h, pS2, pQ2, g2, be2, nullptr, nullptr, nullptr, pX3,
        N, HIDDEN, N_CLASSES, NC_PAD);
    k_gather40_lsm<<<gatherBlocks, 256>>>(out, pX3, b3, N);
}